// round 5
// baseline (speedup 1.0000x reference)
#include <cuda_runtime.h>

typedef unsigned long long ull;
typedef unsigned int uint;

#define BB   8
#define NP   4096
#define CI   64
#define CO   64
#define KK   20

// ---------------- scratch (static device globals; no runtime allocation) ----
static __device__ float g_xx[BB * NP];                  // squared norms
static __device__ int   g_idx[BB * NP * KK];            // knn indices
static __device__ float g_a [BB * NP * CO];             // (W1-W2) @ x_n
static __device__ float g_cc[BB * NP * CO];             // W2 @ x_m
static __device__ float g_hmax[(size_t)BB * NP * CO];
static __device__ float g_hmin[(size_t)BB * NP * CO];
static __device__ float g_sum[CO];
static __device__ float g_sumsq[CO];
static __device__ float g_scale[CO];
static __device__ float g_bias[CO];

// ---------------- helpers ---------------------------------------------------
__device__ __forceinline__ ull ffma2(ull a, ull b, ull c) {
    ull d;
    asm("fma.rn.f32x2 %0, %1, %2, %3;" : "=l"(d) : "l"(a), "l"(b), "l"(c));
    return d;
}
__device__ __forceinline__ ull pack2(float lo, float hi) {
    return (ull)__float_as_uint(lo) | ((ull)__float_as_uint(hi) << 32);
}
__device__ __forceinline__ void cp16(uint s, const void* g) {
    asm volatile("cp.async.cg.shared.global [%0], [%1], 16;" :: "r"(s), "l"(g));
}
__device__ __forceinline__ void cp_commit() {
    asm volatile("cp.async.commit_group;");
}
__device__ __forceinline__ void cp_wait0() {
    asm volatile("cp.async.wait_group 0;" ::: "memory");
}

// min-heap (size 20) replace-root + sift-down
__device__ __forceinline__ void hrep(float* v, int* ix, float nv, int ni) {
    int p = 0;
    while (true) {
        int c = 2 * p + 1;
        if (c >= KK) break;
        if (c + 1 < KK && v[c + 1] < v[c]) c++;
        if (v[c] >= nv) break;
        v[p] = v[c]; ix[p] = ix[c]; p = c;
    }
    v[p] = nv; ix[p] = ni;
}

// ---------------- 0: zero channel stats -------------------------------------
__global__ void zero_stats_k() {
    int t = threadIdx.x;
    if (t < CO) { g_sum[t] = 0.f; g_sumsq[t] = 0.f; }
}

// ---------------- 1: squared norms ------------------------------------------
__global__ void xx_k(const float* __restrict__ x) {
    int g = blockIdx.x * blockDim.x + threadIdx.x;     // 0..BB*NP-1
    int b = g >> 12;
    int n = g & (NP - 1);
    const float* xb = x + (size_t)b * CI * NP + n;
    float s = 0.f;
    #pragma unroll
    for (int c = 0; c < CI; ++c) { float v = xb[c * NP]; s = fmaf(v, v, s); }
    g_xx[g] = s;
}

// ---------------- 2: a = (W1-W2)@x_n,  c = W2@x_n ---------------------------
__global__ __launch_bounds__(256) void ac_k(const float* __restrict__ x,
                                            const float* __restrict__ W) {
    __shared__ float sWd[CI * CO];   // [c][o]
    __shared__ float sW2[CI * CO];   // [c][o]
    int tid = threadIdx.x;
    for (int i = tid; i < CI * CO; i += 256) {
        int o = i >> 6, c = i & 63;
        float w1 = W[o * 128 + c];
        float w2 = W[o * 128 + 64 + c];
        sWd[c * CO + o] = w1 - w2;
        sW2[c * CO + o] = w2;
    }
    __syncthreads();
    int b  = blockIdx.y;
    int n  = blockIdx.x * 128 + (tid & 127);
    int o0 = (tid >> 7) * 32;
    float aa[32], cc[32];
    #pragma unroll
    for (int j = 0; j < 32; ++j) { aa[j] = 0.f; cc[j] = 0.f; }
    const float* xb = x + (size_t)b * CI * NP + n;
    for (int c = 0; c < CI; ++c) {
        float xv = xb[c * NP];
        const float4* wd4 = (const float4*)(sWd + c * CO + o0);
        const float4* w24 = (const float4*)(sW2 + c * CO + o0);
        #pragma unroll
        for (int j4 = 0; j4 < 8; ++j4) {
            float4 wd = wd4[j4], w2 = w24[j4];
            aa[j4*4+0] = fmaf(xv, wd.x, aa[j4*4+0]);
            aa[j4*4+1] = fmaf(xv, wd.y, aa[j4*4+1]);
            aa[j4*4+2] = fmaf(xv, wd.z, aa[j4*4+2]);
            aa[j4*4+3] = fmaf(xv, wd.w, aa[j4*4+3]);
            cc[j4*4+0] = fmaf(xv, w2.x, cc[j4*4+0]);
            cc[j4*4+1] = fmaf(xv, w2.y, cc[j4*4+1]);
            cc[j4*4+2] = fmaf(xv, w2.z, cc[j4*4+2]);
            cc[j4*4+3] = fmaf(xv, w2.w, cc[j4*4+3]);
        }
    }
    size_t base = ((size_t)b * NP + n) * CO + o0;
    #pragma unroll
    for (int j = 0; j < 32; ++j) { g_a[base + j] = aa[j]; g_cc[base + j] = cc[j]; }
}

// ---------------- 3: fused Gram + top-20 select ------------------------------
// One block per (batch, 128-row n strip). Loops over 32 m-tiles of 128.
// Scores s = inner(n,m) - 0.5*xx[m] computed with f32x2 packed FMAs, staged in
// smem, merged into per-(row,half) 20-min-heaps, pairwise-merged at the end.
// Dynamic smem layout:
//   sQ     : 64*128 f32   (32 KB)   x[n-strip], all channels, loaded once
//   sP[2]  : 64*128 f32 x2 (64 KB)  x[m-tile], double-buffered via cp.async
//   sS     : 128*65 ull   (66.6 KB) score tile, pairs along m
//   hV, hI : 256*20 each  (40 KB)   per (row,half) heaps
#define SQ_OFF  0
#define SP_OFF  (64*128*4)
#define SS_OFF  (SP_OFF + 2*64*128*4)
#define HV_OFF  (SS_OFF + 128*65*8)
#define HI_OFF  (HV_OFF + 256*KK*4)
#define SMEM_TOTAL (HI_OFF + 256*KK*4)

__global__ __launch_bounds__(256, 1) void gramsel_k(const float* __restrict__ x) {
    extern __shared__ char smraw[];
    float* sQ  = (float*)(smraw + SQ_OFF);
    float* sP0 = (float*)(smraw + SP_OFF);
    float* sP1 = sP0 + 64 * 128;
    ull*   sS  = (ull*)(smraw + SS_OFF);
    float* hV  = (float*)(smraw + HV_OFF);
    int*   hI  = (int*)(smraw + HI_OFF);

    const int tid = threadIdx.x;
    const int b   = blockIdx.y;
    const int n0  = blockIdx.x << 7;
    const float* xb = x + (size_t)b * CI * NP;

    // prefetch m-tile 0 into sP0
    {
        uint sp = (uint)__cvta_generic_to_shared(sP0);
        #pragma unroll
        for (int k = 0; k < 8; ++k) {
            int i = tid + k * 256;           // 0..2047
            int c = i >> 5, j = (i & 31) << 2;
            cp16(sp + (uint)(c * 128 + j) * 4, xb + (size_t)c * NP + j);
        }
        cp_commit();
    }
    // load sQ (whole n-strip, all channels)
    #pragma unroll
    for (int k = 0; k < 8; ++k) {
        int i = tid + k * 256;
        int c = i >> 5, j = (i & 31) << 2;
        *(float4*)(sQ + c * 128 + j) = *(const float4*)(xb + (size_t)c * NP + n0 + j);
    }
    // init heaps
    float* hv = hV + tid * KK;
    int*   hi = hI + tid * KK;
    #pragma unroll
    for (int k = 0; k < KK; ++k) { hv[k] = __int_as_float(0xff800000); hi[k] = 0; }

    const int tx = tid & 15;      // m-pair: p = tx + 16*g  ->  m = 2p, 2p+1
    const int ty = tid >> 4;      // n: row = ty*8 + i
    const int r  = tid & 127;     // scan row
    const int h  = tid >> 7;      // scan half
    const float* xxg = g_xx + b * NP;

    for (int t = 0; t < 32; ++t) {
        const int m0 = t << 7;
        const float* sPc = (t & 1) ? sP1 : sP0;
        cp_wait0();
        __syncthreads();          // sP[cur] ready; previous scan done (sS free)

        if (t < 31) {             // prefetch next tile
            float* nxt = (t & 1) ? sP0 : sP1;
            uint sp = (uint)__cvta_generic_to_shared(nxt);
            const float* src = xb + (m0 + 128);
            #pragma unroll
            for (int k = 0; k < 8; ++k) {
                int i = tid + k * 256;
                int c = i >> 5, j = (i & 31) << 2;
                cp16(sp + (uint)(c * 128 + j) * 4, src + (size_t)c * NP + j);
            }
            cp_commit();
        }

        // accumulators initialized to -0.5*xx[m] (folds the epilogue subtract)
        ull acc[8][4];
        #pragma unroll
        for (int g = 0; g < 4; ++g) {
            float2 w = *(const float2*)(xxg + m0 + ((tx + (g << 4)) << 1));
            ull init = pack2(-0.5f * w.x, -0.5f * w.y);
            #pragma unroll
            for (int i = 0; i < 8; ++i) acc[i][g] = init;
        }
        #pragma unroll 4
        for (int c = 0; c < CI; ++c) {
            ull q[8], p[4];
            #pragma unroll
            for (int i = 0; i < 8; ++i) {
                unsigned u = __float_as_uint(sQ[c * 128 + ty * 8 + i]);
                q[i] = (ull)u | ((ull)u << 32);
            }
            const ull* pp = (const ull*)(sPc + c * 128);
            #pragma unroll
            for (int g = 0; g < 4; ++g) p[g] = pp[tx + (g << 4)];
            #pragma unroll
            for (int i = 0; i < 8; ++i)
                #pragma unroll
                for (int g = 0; g < 4; ++g) acc[i][g] = ffma2(q[i], p[g], acc[i][g]);
        }
        // scores -> smem
        #pragma unroll
        for (int i = 0; i < 8; ++i) {
            ull* row = sS + (ty * 8 + i) * 65;
            #pragma unroll
            for (int g = 0; g < 4; ++g) row[tx + (g << 4)] = acc[i][g];
        }
        __syncthreads();

        // scan: thread (r,h) owns pairs [h*32, h*32+32) of row r
        {
            const ull* rowp = sS + r * 65 + (h << 5);
            int mbase = m0 + (h << 6);
            #pragma unroll 4
            for (int j = 0; j < 32; ++j) {
                ull u = rowp[j];
                float lo = __uint_as_float((unsigned)u);
                float hi2 = __uint_as_float((unsigned)(u >> 32));
                if (lo  > hv[0]) hrep(hv, hi, lo,  mbase + (j << 1));
                if (hi2 > hv[0]) hrep(hv, hi, hi2, mbase + (j << 1) + 1);
            }
        }
    }
    __syncthreads();
    // merge half-heaps and emit indices
    if (h == 0) {
        const float* pv = hV + (tid + 128) * KK;
        const int*   pi = hI + (tid + 128) * KK;
        #pragma unroll
        for (int k = 0; k < KK; ++k)
            if (pv[k] > hv[0]) hrep(hv, hi, pv[k], pi[k]);
        int* op = g_idx + ((size_t)b * NP + n0 + r) * KK;
        #pragma unroll
        for (int k = 0; k < KK; ++k) op[k] = hi[k];
    }
}

// ---------------- 4: per-(b,n,o) max/min over k + channel stats -------------
__global__ __launch_bounds__(256) void maxmin_k() {
    __shared__ float sSum[CO], sSq[CO];
    int tid = threadIdx.x;
    if (tid < CO) { sSum[tid] = 0.f; sSq[tid] = 0.f; }
    __syncthreads();
    int o = tid & 63;
    int r = blockIdx.x * 4 + (tid >> 6);       // row = b*NP+n
    int b = r >> 12;
    float av = g_a[(size_t)r * CO + o];
    const int* ip = g_idx + (size_t)r * KK;
    const float PINF = __int_as_float(0x7f800000);
    float mx = -PINF, mn = PINF, s = 0.f, s2 = 0.f;
    #pragma unroll
    for (int k = 0; k < KK; ++k) {
        int j = ip[k];
        float e = av + g_cc[((size_t)(b << 12) + j) * CO + o];
        mx = fmaxf(mx, e); mn = fminf(mn, e);
        s += e; s2 = fmaf(e, e, s2);
    }
    g_hmax[(size_t)r * CO + o] = mx;
    g_hmin[(size_t)r * CO + o] = mn;
    atomicAdd(&sSum[o], s);
    atomicAdd(&sSq[o], s2);
    __syncthreads();
    if (tid < CO) {
        atomicAdd(&g_sum[tid], sSum[tid]);
        atomicAdd(&g_sumsq[tid], sSq[tid]);
    }
}

// ---------------- 5: finalize batchnorm affine ------------------------------
__global__ void finalize_k(const float* __restrict__ gamma,
                           const float* __restrict__ beta) {
    int o = threadIdx.x;
    const float cnt = (float)BB * NP * KK;
    float mean = g_sum[o] / cnt;
    float var  = g_sumsq[o] / cnt - mean * mean;
    float sc   = gamma[o] * rsqrtf(var + 1e-5f);
    g_scale[o] = sc;
    g_bias[o]  = fmaf(-mean, sc, beta[o]);
}

// ---------------- 6: output (affine + leaky + transpose to (B,CO,N)) --------
__global__ __launch_bounds__(256) void out_k(float* __restrict__ out) {
    __shared__ float sm[64][65];
    int tid = threadIdx.x;
    int b = blockIdx.y, n0 = blockIdx.x * 64;
    #pragma unroll
    for (int it = 0; it < 16; ++it) {
        int i = it * 4 + (tid >> 6), o = tid & 63;
        float sc = g_scale[o];
        size_t idx = ((size_t)b * NP + n0 + i) * CO + o;
        float h = (sc >= 0.f) ? g_hmax[idx] : g_hmin[idx];
        float v = fmaf(sc, h, g_bias[o]);
        sm[i][o] = (v >= 0.f) ? v : 0.2f * v;
    }
    __syncthreads();
    #pragma unroll
    for (int it = 0; it < 16; ++it) {
        int o = it * 4 + (tid >> 6), n = tid & 63;
        out[((size_t)b * CO + o) * NP + n0 + n] = sm[n][o];
    }
}

// ---------------- launch -----------------------------------------------------
extern "C" void kernel_launch(void* const* d_in, const int* in_sizes, int n_in,
                              void* d_out, int out_size) {
    const float* x     = (const float*)d_in[0];
    const float* W     = (const float*)d_in[1];
    const float* gamma = (const float*)d_in[2];
    const float* beta  = (const float*)d_in[3];
    float* out = (float*)d_out;

    cudaFuncSetAttribute(gramsel_k, cudaFuncAttributeMaxDynamicSharedMemorySize,
                         SMEM_TOTAL);

    zero_stats_k<<<1, 64>>>();
    xx_k<<<(BB * NP) / 256, 256>>>(x);
    ac_k<<<dim3(NP / 128, BB), 256>>>(x, W);
    gramsel_k<<<dim3(NP / 128, BB), 256, SMEM_TOTAL>>>(x);
    maxmin_k<<<(BB * NP) / 4, 256>>>();
    finalize_k<<<1, 64>>>(gamma, beta);
    out_k<<<dim3(NP / 64, BB), 256>>>(out);
}

// round 6
// speedup vs baseline: 2.0786x; 2.0786x over previous
#include <cuda_runtime.h>

typedef unsigned long long ull;
typedef unsigned int uint;

#define BB   8
#define NP   4096
#define CI   64
#define CO   64
#define KK   20

// ---------------- scratch (static device globals; no runtime allocation) ----
static __device__ float g_dist[(size_t)BB * NP * NP];   // 512 MB score rows
static __device__ float g_tmax[(size_t)BB * NP * 32];   // per-(row, m-tile) max
static __device__ float g_xx[BB * NP];                  // squared norms
static __device__ int   g_idx[BB * NP * KK];            // knn indices
static __device__ float g_a [BB * NP * CO];             // (W1-W2) @ x_n
static __device__ float g_cc[BB * NP * CO];             // W2 @ x_m
static __device__ float g_hmax[(size_t)BB * NP * CO];
static __device__ float g_hmin[(size_t)BB * NP * CO];
static __device__ float g_sum[CO];
static __device__ float g_sumsq[CO];
static __device__ float g_scale[CO];
static __device__ float g_bias[CO];

// ---------------- helpers ---------------------------------------------------
__device__ __forceinline__ ull ffma2(ull a, ull b, ull c) {
    ull d;
    asm("fma.rn.f32x2 %0, %1, %2, %3;" : "=l"(d) : "l"(a), "l"(b), "l"(c));
    return d;
}
__device__ __forceinline__ ull pack2(float lo, float hi) {
    return (ull)__float_as_uint(lo) | ((ull)__float_as_uint(hi) << 32);
}
__device__ __forceinline__ void cp16(uint s, const void* g) {
    asm volatile("cp.async.cg.shared.global [%0], [%1], 16;" :: "r"(s), "l"(g));
}
__device__ __forceinline__ void cp_commit() {
    asm volatile("cp.async.commit_group;");
}
__device__ __forceinline__ void cp_wait0() {
    asm volatile("cp.async.wait_group 0;" ::: "memory");
}

// ---------------- 0: zero channel stats -------------------------------------
__global__ void zero_stats_k() {
    int t = threadIdx.x;
    if (t < CO) { g_sum[t] = 0.f; g_sumsq[t] = 0.f; }
}

// ---------------- 1: squared norms ------------------------------------------
__global__ void xx_k(const float* __restrict__ x) {
    int g = blockIdx.x * blockDim.x + threadIdx.x;     // 0..BB*NP-1
    int b = g >> 12;
    int n = g & (NP - 1);
    const float* xb = x + (size_t)b * CI * NP + n;
    float s = 0.f;
    #pragma unroll
    for (int c = 0; c < CI; ++c) { float v = xb[c * NP]; s = fmaf(v, v, s); }
    g_xx[g] = s;
}

// ---------------- 2: a = (W1-W2)@x_n,  c = W2@x_n ---------------------------
__global__ __launch_bounds__(256) void ac_k(const float* __restrict__ x,
                                            const float* __restrict__ W) {
    __shared__ float sWd[CI * CO];   // [c][o]
    __shared__ float sW2[CI * CO];   // [c][o]
    int tid = threadIdx.x;
    for (int i = tid; i < CI * CO; i += 256) {
        int o = i >> 6, c = i & 63;
        float w1 = W[o * 128 + c];
        float w2 = W[o * 128 + 64 + c];
        sWd[c * CO + o] = w1 - w2;
        sW2[c * CO + o] = w2;
    }
    __syncthreads();
    int b  = blockIdx.y;
    int n  = blockIdx.x * 128 + (tid & 127);
    int o0 = (tid >> 7) * 32;
    float aa[32], cc[32];
    #pragma unroll
    for (int j = 0; j < 32; ++j) { aa[j] = 0.f; cc[j] = 0.f; }
    const float* xb = x + (size_t)b * CI * NP + n;
    for (int c = 0; c < CI; ++c) {
        float xv = xb[c * NP];
        const float4* wd4 = (const float4*)(sWd + c * CO + o0);
        const float4* w24 = (const float4*)(sW2 + c * CO + o0);
        #pragma unroll
        for (int j4 = 0; j4 < 8; ++j4) {
            float4 wd = wd4[j4], w2 = w24[j4];
            aa[j4*4+0] = fmaf(xv, wd.x, aa[j4*4+0]);
            aa[j4*4+1] = fmaf(xv, wd.y, aa[j4*4+1]);
            aa[j4*4+2] = fmaf(xv, wd.z, aa[j4*4+2]);
            aa[j4*4+3] = fmaf(xv, wd.w, aa[j4*4+3]);
            cc[j4*4+0] = fmaf(xv, w2.x, cc[j4*4+0]);
            cc[j4*4+1] = fmaf(xv, w2.y, cc[j4*4+1]);
            cc[j4*4+2] = fmaf(xv, w2.z, cc[j4*4+2]);
            cc[j4*4+3] = fmaf(xv, w2.w, cc[j4*4+3]);
        }
    }
    size_t base = ((size_t)b * NP + n) * CO + o0;
    #pragma unroll
    for (int j = 0; j < 32; ++j) { g_a[base + j] = aa[j]; g_cc[base + j] = cc[j]; }
}

// ---------------- 3: Gram scores + per-(row,tile) max ------------------------
// One block per (m-tile, n-tile, b). All 64 channels resident in smem (one
// cp.async load phase, one barrier), 8n x 8m f32x2 microtile, accumulators
// pre-initialized with -0.5*xx[m]. Epilogue stores the 128x128 score tile and
// a per-row tile-max (16-lane shfl reduce) for the pruned selection kernel.
#define GS_TOTAL (2 * 64 * 128 * 4)   // sQ + sP, 64 KB dynamic smem

__global__ __launch_bounds__(256, 2) void gram_k(const float* __restrict__ x) {
    extern __shared__ char smraw[];
    float* sQ = (float*)smraw;              // [c][128] queries (n tile)
    float* sP = sQ + 64 * 128;              // [c][128] points  (m tile), pair view
    const int tid = threadIdx.x;
    const int b   = blockIdx.z;
    const int n0  = blockIdx.y << 7;
    const int m0  = blockIdx.x << 7;
    const float* xb = x + (size_t)b * CI * NP;

    {
        uint sq = (uint)__cvta_generic_to_shared(sQ);
        uint sp = (uint)__cvta_generic_to_shared(sP);
        #pragma unroll
        for (int k = 0; k < 8; ++k) {
            int i = k * 256 + tid;           // 0..2047
            int c = i >> 5, j = (i & 31) << 2;
            uint off = (uint)(c * 128 + j) * 4;
            cp16(sq + off, xb + (size_t)c * NP + n0 + j);
            cp16(sp + off, xb + (size_t)c * NP + m0 + j);
        }
        cp_commit();
    }

    const int tx = tid & 15;      // m-pair: p = tx + 16*g  ->  m = 2p, 2p+1
    const int ty = tid >> 4;      // n: row = ty*8 + i
    const float* xxg = g_xx + b * NP + m0;

    ull acc[8][4];
    #pragma unroll
    for (int g = 0; g < 4; ++g) {
        float2 w = *(const float2*)(xxg + ((tx + (g << 4)) << 1));
        ull init = pack2(-0.5f * w.x, -0.5f * w.y);
        #pragma unroll
        for (int i = 0; i < 8; ++i) acc[i][g] = init;
    }

    cp_wait0();
    __syncthreads();

    #pragma unroll 4
    for (int c = 0; c < CI; ++c) {
        ull q[8], p[4];
        #pragma unroll
        for (int i = 0; i < 8; ++i) {
            unsigned u = __float_as_uint(sQ[c * 128 + ty * 8 + i]);
            q[i] = (ull)u | ((ull)u << 32);
        }
        const ull* pp = (const ull*)(sP + c * 128);
        #pragma unroll
        for (int g = 0; g < 4; ++g) p[g] = pp[tx + (g << 4)];
        #pragma unroll
        for (int i = 0; i < 8; ++i)
            #pragma unroll
            for (int g = 0; g < 4; ++g) acc[i][g] = ffma2(q[i], p[g], acc[i][g]);
    }

    size_t rb = (size_t)b * NP + n0 + ty * 8;
    #pragma unroll
    for (int i = 0; i < 8; ++i) {
        float rmax = __int_as_float(0xff800000);
        #pragma unroll
        for (int g = 0; g < 4; ++g) {
            int mp = tx + (g << 4);
            float2 v;
            v.x = __uint_as_float((unsigned)(acc[i][g]));
            v.y = __uint_as_float((unsigned)(acc[i][g] >> 32));
            *(float2*)(g_dist + (rb + i) * NP + m0 + (mp << 1)) = v;
            rmax = fmaxf(rmax, fmaxf(v.x, v.y));
        }
        #pragma unroll
        for (int off = 8; off; off >>= 1)
            rmax = fmaxf(rmax, __shfl_xor_sync(0xffffffffu, rmax, off));
        if (tx == 0) g_tmax[(rb + i) * 32 + blockIdx.x] = rmax;
    }
}

// ---------------- 4: pruned top-20 select -----------------------------------
// Warp per row. Visit m-tiles in descending tile-max order; stop when the best
// remaining tile-max <= current 20th value. Top-20 kept as a warp-distributed
// sorted list (lanes 0..19, descending).
__global__ __launch_bounds__(256) void select2_k() {
    const int row  = (blockIdx.x * 256 + threadIdx.x) >> 5;
    const int lane = threadIdx.x & 31;
    const float NEG = __int_as_float(0xff800000);
    const unsigned FULL = 0xffffffffu;

    float tmv = g_tmax[(size_t)row * 32 + lane];   // one tile-max per lane
    float lv = NEG; int li = 0;                     // distributed sorted list
    float thr = NEG;                                // = lv[19]
    const float* base = g_dist + (size_t)row * NP;

    for (int it = 0; it < 32; ++it) {
        // warp argmax over remaining tile maxima (tie -> lower tile id)
        float bv = tmv; int bt = lane;
        #pragma unroll
        for (int off = 16; off; off >>= 1) {
            float ov = __shfl_xor_sync(FULL, bv, off);
            int   ot = __shfl_xor_sync(FULL, bt, off);
            if (ov > bv || (ov == bv && ot < bt)) { bv = ov; bt = ot; }
        }
        if (bv <= thr) break;                      // nothing left can enter top-20
        if (lane == bt) tmv = NEG;                 // mark visited

        float4 v4 = *(const float4*)(base + (bt << 7) + (lane << 2));
        int ib = (bt << 7) + (lane << 2);
        #pragma unroll
        for (int e = 0; e < 4; ++e) {
            float v = (e == 0) ? v4.x : (e == 1) ? v4.y : (e == 2) ? v4.z : v4.w;
            bool pend = (v > thr);
            while (true) {
                unsigned ball = __ballot_sync(FULL, pend);
                if (!ball) break;
                int   src = __ffs(ball) - 1;
                float cv  = __shfl_sync(FULL, v, src);
                int   ci  = __shfl_sync(FULL, ib + e, src);
                // insert (cv,ci) into the sorted list
                unsigned gb = __ballot_sync(FULL, lane < KK && lv >= cv);
                int pos = __popc(gb);
                float sv = __shfl_up_sync(FULL, lv, 1);
                int   si = __shfl_up_sync(FULL, li, 1);
                if (lane > pos)       { lv = sv; li = si; }
                else if (lane == pos) { lv = cv; li = ci; }
                thr = __shfl_sync(FULL, lv, KK - 1);
                if (lane == src) pend = false;
                pend = pend && (v > thr);
            }
        }
    }
    if (lane < KK) g_idx[(size_t)row * KK + lane] = li;
}

// ---------------- 5: per-(b,n,o) max/min over k + channel stats -------------
__global__ __launch_bounds__(256) void maxmin_k() {
    __shared__ float sSum[CO], sSq[CO];
    int tid = threadIdx.x;
    if (tid < CO) { sSum[tid] = 0.f; sSq[tid] = 0.f; }
    __syncthreads();
    int o = tid & 63;
    int r = blockIdx.x * 4 + (tid >> 6);       // row = b*NP+n
    int b = r >> 12;
    float av = g_a[(size_t)r * CO + o];
    const int* ip = g_idx + (size_t)r * KK;
    const float PINF = __int_as_float(0x7f800000);
    float mx = -PINF, mn = PINF, s = 0.f, s2 = 0.f;
    #pragma unroll
    for (int k = 0; k < KK; ++k) {
        int j = ip[k];
        float e = av + g_cc[((size_t)(b << 12) + j) * CO + o];
        mx = fmaxf(mx, e); mn = fminf(mn, e);
        s += e; s2 = fmaf(e, e, s2);
    }
    g_hmax[(size_t)r * CO + o] = mx;
    g_hmin[(size_t)r * CO + o] = mn;
    atomicAdd(&sSum[o], s);
    atomicAdd(&sSq[o], s2);
    __syncthreads();
    if (tid < CO) {
        atomicAdd(&g_sum[tid], sSum[tid]);
        atomicAdd(&g_sumsq[tid], sSq[tid]);
    }
}

// ---------------- 6: finalize batchnorm affine ------------------------------
__global__ void finalize_k(const float* __restrict__ gamma,
                           const float* __restrict__ beta) {
    int o = threadIdx.x;
    const float cnt = (float)BB * NP * KK;
    float mean = g_sum[o] / cnt;
    float var  = g_sumsq[o] / cnt - mean * mean;
    float sc   = gamma[o] * rsqrtf(var + 1e-5f);
    g_scale[o] = sc;
    g_bias[o]  = fmaf(-mean, sc, beta[o]);
}

// ---------------- 7: output (affine + leaky + transpose to (B,CO,N)) --------
__global__ __launch_bounds__(256) void out_k(float* __restrict__ out) {
    __shared__ float sm[64][65];
    int tid = threadIdx.x;
    int b = blockIdx.y, n0 = blockIdx.x * 64;
    #pragma unroll
    for (int it = 0; it < 16; ++it) {
        int i = it * 4 + (tid >> 6), o = tid & 63;
        float sc = g_scale[o];
        size_t idx = ((size_t)b * NP + n0 + i) * CO + o;
        float h = (sc >= 0.f) ? g_hmax[idx] : g_hmin[idx];
        float v = fmaf(sc, h, g_bias[o]);
        sm[i][o] = (v >= 0.f) ? v : 0.2f * v;
    }
    __syncthreads();
    #pragma unroll
    for (int it = 0; it < 16; ++it) {
        int o = it * 4 + (tid >> 6), n = tid & 63;
        out[((size_t)b * CO + o) * NP + n0 + n] = sm[n][o];
    }
}

// ---------------- launch -----------------------------------------------------
extern "C" void kernel_launch(void* const* d_in, const int* in_sizes, int n_in,
                              void* d_out, int out_size) {
    const float* x     = (const float*)d_in[0];
    const float* W     = (const float*)d_in[1];
    const float* gamma = (const float*)d_in[2];
    const float* beta  = (const float*)d_in[3];
    float* out = (float*)d_out;

    cudaFuncSetAttribute(gram_k, cudaFuncAttributeMaxDynamicSharedMemorySize,
                         GS_TOTAL);

    zero_stats_k<<<1, 64>>>();
    xx_k<<<(BB * NP) / 256, 256>>>(x);
    ac_k<<<dim3(NP / 128, BB), 256>>>(x, W);
    gram_k<<<dim3(NP / 128, NP / 128, BB), 256, GS_TOTAL>>>(x);
    select2_k<<<(BB * NP) / 8, 256>>>();
    maxmin_k<<<(BB * NP) / 4, 256>>>();
    finalize_k<<<1, 64>>>(gamma, beta);
    out_k<<<dim3(NP / 64, BB), 256>>>(out);
}

// round 8
// speedup vs baseline: 2.5265x; 1.2155x over previous
#include <cuda_runtime.h>

typedef unsigned long long ull;
typedef unsigned int uint;

#define BB   8
#define NP   4096
#define CI   64
#define CO   64
#define KK   20
#define NTILE 32
#define NPAIRS (NTILE * (NTILE + 1) / 2)   // 528
#define TSTRIDE 132                         // transposed-tile stride (16B-aligned rows)

// ---------------- scratch (static device globals; no runtime allocation) ----
static __device__ float g_dist[(size_t)BB * NP * NP];   // 512 MB score rows
static __device__ float g_tmax[(size_t)BB * NP * NTILE];// per-(row, m-tile) max
static __device__ float g_xx[BB * NP];                  // squared norms
static __device__ int   g_idx[BB * NP * KK];            // knn indices
static __device__ float g_a [BB * NP * CO];             // (W1-W2) @ x_n
static __device__ float g_cc[BB * NP * CO];             // W2 @ x_m
static __device__ float g_hmax[(size_t)BB * NP * CO];
static __device__ float g_hmin[(size_t)BB * NP * CO];
static __device__ float g_sum[CO];
static __device__ float g_sumsq[CO];
static __device__ float g_scale[CO];
static __device__ float g_bias[CO];

// ---------------- helpers ---------------------------------------------------
__device__ __forceinline__ ull ffma2(ull a, ull b, ull c) {
    ull d;
    asm("fma.rn.f32x2 %0, %1, %2, %3;" : "=l"(d) : "l"(a), "l"(b), "l"(c));
    return d;
}
__device__ __forceinline__ void cp16(uint s, const void* g) {
    asm volatile("cp.async.cg.shared.global [%0], [%1], 16;" :: "r"(s), "l"(g));
}
__device__ __forceinline__ void cp_commit() {
    asm volatile("cp.async.commit_group;");
}
__device__ __forceinline__ void cp_wait0() {
    asm volatile("cp.async.wait_group 0;" ::: "memory");
}

// ---------------- 0: zero channel stats -------------------------------------
__global__ void zero_stats_k() {
    int t = threadIdx.x;
    if (t < CO) { g_sum[t] = 0.f; g_sumsq[t] = 0.f; }
}

// ---------------- 1: squared norms ------------------------------------------
__global__ void xx_k(const float* __restrict__ x) {
    int g = blockIdx.x * blockDim.x + threadIdx.x;     // 0..BB*NP-1
    int b = g >> 12;
    int n = g & (NP - 1);
    const float* xb = x + (size_t)b * CI * NP + n;
    float s = 0.f;
    #pragma unroll
    for (int c = 0; c < CI; ++c) { float v = xb[c * NP]; s = fmaf(v, v, s); }
    g_xx[g] = s;
}

// ---------------- 2: a = (W1-W2)@x_n,  c = W2@x_n ---------------------------
__global__ __launch_bounds__(256) void ac_k(const float* __restrict__ x,
                                            const float* __restrict__ W) {
    __shared__ float sWd[CI * CO];   // [c][o]
    __shared__ float sW2[CI * CO];   // [c][o]
    int tid = threadIdx.x;
    for (int i = tid; i < CI * CO; i += 256) {
        int o = i >> 6, c = i & 63;
        float w1 = W[o * 128 + c];
        float w2 = W[o * 128 + 64 + c];
        sWd[c * CO + o] = w1 - w2;
        sW2[c * CO + o] = w2;
    }
    __syncthreads();
    int b  = blockIdx.y;
    int n  = blockIdx.x * 128 + (tid & 127);
    int o0 = (tid >> 7) * 32;
    float aa[32], cc[32];
    #pragma unroll
    for (int j = 0; j < 32; ++j) { aa[j] = 0.f; cc[j] = 0.f; }
    const float* xb = x + (size_t)b * CI * NP + n;
    for (int c = 0; c < CI; ++c) {
        float xv = xb[c * NP];
        const float4* wd4 = (const float4*)(sWd + c * CO + o0);
        const float4* w24 = (const float4*)(sW2 + c * CO + o0);
        #pragma unroll
        for (int j4 = 0; j4 < 8; ++j4) {
            float4 wd = wd4[j4], w2 = w24[j4];
            aa[j4*4+0] = fmaf(xv, wd.x, aa[j4*4+0]);
            aa[j4*4+1] = fmaf(xv, wd.y, aa[j4*4+1]);
            aa[j4*4+2] = fmaf(xv, wd.z, aa[j4*4+2]);
            aa[j4*4+3] = fmaf(xv, wd.w, aa[j4*4+3]);
            cc[j4*4+0] = fmaf(xv, w2.x, cc[j4*4+0]);
            cc[j4*4+1] = fmaf(xv, w2.y, cc[j4*4+1]);
            cc[j4*4+2] = fmaf(xv, w2.z, cc[j4*4+2]);
            cc[j4*4+3] = fmaf(xv, w2.w, cc[j4*4+3]);
        }
    }
    size_t base = ((size_t)b * NP + n) * CO + o0;
    #pragma unroll
    for (int j = 0; j < 32; ++j) { g_a[base + j] = aa[j]; g_cc[base + j] = cc[j]; }
}

// ---------------- 3: Gram (triangular tile pairs) + per-(row,tile) max ------
// One block per unordered tile pair (ti<=tj) and batch. Computes the 128x128
// inner-product tile once; writes BOTH orientations (score = inner - 0.5*xx of
// the column point), transposed one staged through smem for coalescing.
#define GS_TOTAL (128 * TSTRIDE * 4)    // 67,584 B (>= sQ 32KB + sP 32KB)

__global__ __launch_bounds__(256, 2) void gram_k(const float* __restrict__ x) {
    extern __shared__ char smraw[];
    float* sQ = (float*)smraw;              // [c][128] rows-tile (ti)
    float* sP = sQ + 64 * 128;              // [c][128] cols-tile (tj)
    const int tid = threadIdx.x;
    const int b   = blockIdx.y;
    // decode pair index -> (ti, tj), ti <= tj, p = tj*(tj+1)/2 + ti
    int p  = blockIdx.x;
    int tj = (int)((sqrtf(8.f * p + 1.f) - 1.f) * 0.5f);
    while ((tj + 1) * (tj + 2) / 2 <= p) ++tj;
    while (tj * (tj + 1) / 2 > p) --tj;
    int ti = p - tj * (tj + 1) / 2;
    const int n0 = ti << 7;
    const int m0 = tj << 7;
    const float* xb = x + (size_t)b * CI * NP;

    {
        uint sq = (uint)__cvta_generic_to_shared(sQ);
        uint sp = (uint)__cvta_generic_to_shared(sP);
        #pragma unroll
        for (int k = 0; k < 8; ++k) {
            int i = k * 256 + tid;           // 0..2047
            int c = i >> 5, j = (i & 31) << 2;
            uint off = (uint)(c * 128 + j) * 4;
            cp16(sq + off, xb + (size_t)c * NP + n0 + j);
            cp16(sp + off, xb + (size_t)c * NP + m0 + j);
        }
        cp_commit();
    }

    const int tx = tid & 15;      // m-pair: pr = tx + 16*g  ->  m = 2pr, 2pr+1
    const int ty = tid >> 4;      // n: row = ty*8 + i
    const float* xxg = g_xx + b * NP;

    ull acc[8][4];
    #pragma unroll
    for (int i = 0; i < 8; ++i)
        #pragma unroll
        for (int g = 0; g < 4; ++g) acc[i][g] = 0ull;

    cp_wait0();
    __syncthreads();

    #pragma unroll 4
    for (int c = 0; c < CI; ++c) {
        ull q[8], pp[4];
        #pragma unroll
        for (int i = 0; i < 8; ++i) {
            unsigned u = __float_as_uint(sQ[c * 128 + ty * 8 + i]);
            q[i] = (ull)u | ((ull)u << 32);
        }
        const ull* pr = (const ull*)(sP + c * 128);
        #pragma unroll
        for (int g = 0; g < 4; ++g) pp[g] = pr[tx + (g << 4)];
        #pragma unroll
        for (int i = 0; i < 8; ++i)
            #pragma unroll
            for (int g = 0; g < 4; ++g) acc[i][g] = ffma2(q[i], pp[g], acc[i][g]);
    }

    // ---- direct orientation: rows n0-strip, cols m0-strip ----
    size_t rb = (size_t)b * NP + n0 + ty * 8;
    #pragma unroll
    for (int i = 0; i < 8; ++i) {
        float rmax = __int_as_float(0xff800000);
        #pragma unroll
        for (int g = 0; g < 4; ++g) {
            int mp = tx + (g << 4);
            float2 w = *(const float2*)(xxg + m0 + (mp << 1));
            float2 v;
            v.x = fmaf(-0.5f, w.x, __uint_as_float((unsigned)(acc[i][g])));
            v.y = fmaf(-0.5f, w.y, __uint_as_float((unsigned)(acc[i][g] >> 32)));
            *(float2*)(g_dist + (rb + i) * NP + m0 + (mp << 1)) = v;
            rmax = fmaxf(rmax, fmaxf(v.x, v.y));
        }
        #pragma unroll
        for (int off = 8; off; off >>= 1)
            rmax = fmaxf(rmax, __shfl_xor_sync(0xffffffffu, rmax, off));
        if (tx == 0) g_tmax[(rb + i) * NTILE + tj] = rmax;
    }

    // ---- transposed orientation (off-diagonal pairs only) ----
    if (ti != tj) {
        __syncthreads();                       // operand smem now reusable
        float* sT = sQ;                        // [m][n] tile, stride TSTRIDE
        #pragma unroll
        for (int i = 0; i < 8; ++i) {
            int nloc = ty * 8 + i;
            #pragma unroll
            for (int g = 0; g < 4; ++g) {
                int mloc = (tx + (g << 4)) << 1;
                sT[mloc * TSTRIDE + nloc]       = __uint_as_float((unsigned)(acc[i][g]));
                sT[(mloc + 1) * TSTRIDE + nloc] = __uint_as_float((unsigned)(acc[i][g] >> 32));
            }
        }
        __syncthreads();
        int r = tid >> 1, h = tid & 1;         // row m-local, interleaved half
        const float* rowT = sT + r * TSTRIDE;
        float rmax = __int_as_float(0xff800000);
        size_t gb = ((size_t)b * NP + m0 + r) * NP + n0;
        #pragma unroll
        for (int k = 0; k < 16; ++k) {
            int col = (k << 3) + (h << 2);
            float4 v = *(const float4*)(rowT + col);
            float4 xv = *(const float4*)(xxg + n0 + col);
            v.x = fmaf(-0.5f, xv.x, v.x);
            v.y = fmaf(-0.5f, xv.y, v.y);
            v.z = fmaf(-0.5f, xv.z, v.z);
            v.w = fmaf(-0.5f, xv.w, v.w);
            *(float4*)(g_dist + gb + col) = v;
            rmax = fmaxf(rmax, fmaxf(fmaxf(v.x, v.y), fmaxf(v.z, v.w)));
        }
        rmax = fmaxf(rmax, __shfl_xor_sync(0xffffffffu, rmax, 1));
        if (h == 0) g_tmax[((size_t)b * NP + m0 + r) * NTILE + ti] = rmax;
    }
}

// ---------------- 4: pruned top-20 select -----------------------------------
__global__ __launch_bounds__(256) void select2_k() {
    const int row  = (blockIdx.x * 256 + threadIdx.x) >> 5;
    const int lane = threadIdx.x & 31;
    const float NEG = __int_as_float(0xff800000);
    const unsigned FULL = 0xffffffffu;

    float tmv = g_tmax[(size_t)row * NTILE + lane]; // one tile-max per lane
    float lv = NEG; int li = 0;                     // distributed sorted list
    float thr = NEG;                                // = lv[19]
    const float* base = g_dist + (size_t)row * NP;

    for (int it = 0; it < NTILE; ++it) {
        float bv = tmv; int bt = lane;
        #pragma unroll
        for (int off = 16; off; off >>= 1) {
            float ov = __shfl_xor_sync(FULL, bv, off);
            int   ot = __shfl_xor_sync(FULL, bt, off);
            if (ov > bv || (ov == bv && ot < bt)) { bv = ov; bt = ot; }
        }
        if (bv <= thr) break;
        if (lane == bt) tmv = NEG;

        float4 v4 = *(const float4*)(base + (bt << 7) + (lane << 2));
        int ib = (bt << 7) + (lane << 2);
        #pragma unroll
        for (int e = 0; e < 4; ++e) {
            float v = (e == 0) ? v4.x : (e == 1) ? v4.y : (e == 2) ? v4.z : v4.w;
            bool pend = (v > thr);
            while (true) {
                unsigned ball = __ballot_sync(FULL, pend);
                if (!ball) break;
                int   src = __ffs(ball) - 1;
                float cv  = __shfl_sync(FULL, v, src);
                int   ci  = __shfl_sync(FULL, ib + e, src);
                unsigned gb = __ballot_sync(FULL, lane < KK && lv >= cv);
                int pos = __popc(gb);
                float sv = __shfl_up_sync(FULL, lv, 1);
                int   si = __shfl_up_sync(FULL, li, 1);
                if (lane > pos)       { lv = sv; li = si; }
                else if (lane == pos) { lv = cv; li = ci; }
                thr = __shfl_sync(FULL, lv, KK - 1);
                if (lane == src) pend = false;
                pend = pend && (v > thr);
            }
        }
    }
    if (lane < KK) g_idx[(size_t)row * KK + lane] = li;
}

// ---------------- 5: per-(b,n,o) max/min over k + channel stats -------------
__global__ __launch_bounds__(256) void maxmin_k() {
    __shared__ float sSum[CO], sSq[CO];
    int tid = threadIdx.x;
    if (tid < CO) { sSum[tid] = 0.f; sSq[tid] = 0.f; }
    __syncthreads();
    int o = tid & 63;
    int r = blockIdx.x * 4 + (tid >> 6);       // row = b*NP+n
    int b = r >> 12;
    float av = g_a[(size_t)r * CO + o];
    const int* ip = g_idx + (size_t)r * KK;
    const float PINF = __int_as_float(0x7f800000);
    float mx = -PINF, mn = PINF, s = 0.f, s2 = 0.f;
    #pragma unroll
    for (int k = 0; k < KK; ++k) {
        int j = ip[k];
        float e = av + g_cc[((size_t)(b << 12) + j) * CO + o];
        mx = fmaxf(mx, e); mn = fminf(mn, e);
        s += e; s2 = fmaf(e, e, s2);
    }
    g_hmax[(size_t)r * CO + o] = mx;
    g_hmin[(size_t)r * CO + o] = mn;
    atomicAdd(&sSum[o], s);
    atomicAdd(&sSq[o], s2);
    __syncthreads();
    if (tid < CO) {
        atomicAdd(&g_sum[tid], sSum[tid]);
        atomicAdd(&g_sumsq[tid], sSq[tid]);
    }
}

// ---------------- 6: finalize batchnorm affine ------------------------------
__global__ void finalize_k(const float* __restrict__ gamma,
                           const float* __restrict__ beta) {
    int o = threadIdx.x;
    const float cnt = (float)BB * NP * KK;
    float mean = g_sum[o] / cnt;
    float var  = g_sumsq[o] / cnt - mean * mean;
    float sc   = gamma[o] * rsqrtf(var + 1e-5f);
    g_scale[o] = sc;
    g_bias[o]  = fmaf(-mean, sc, beta[o]);
}

// ---------------- 7: output (affine + leaky + transpose to (B,CO,N)) --------
__global__ __launch_bounds__(256) void out_k(float* __restrict__ out) {
    __shared__ float sm[64][65];
    int tid = threadIdx.x;
    int b = blockIdx.y, n0 = blockIdx.x * 64;
    #pragma unroll
    for (int it = 0; it < 16; ++it) {
        int i = it * 4 + (tid >> 6), o = tid & 63;
        float sc = g_scale[o];
        size_t idx = ((size_t)b * NP + n0 + i) * CO + o;
        float h = (sc >= 0.f) ? g_hmax[idx] : g_hmin[idx];
        float v = fmaf(sc, h, g_bias[o]);
        sm[i][o] = (v >= 0.f) ? v : 0.2f * v;
    }
    __syncthreads();
    #pragma unroll
    for (int it = 0; it < 16; ++it) {
        int o = it * 4 + (tid >> 6), n = tid & 63;
        out[((size_t)b * CO + o) * NP + n0 + n] = sm[n][o];
    }
}

// ---------------- launch -----------------------------------------------------
extern "C" void kernel_launch(void* const* d_in, const int* in_sizes, int n_in,
                              void* d_out, int out_size) {
    const float* x     = (const float*)d_in[0];
    const float* W     = (const float*)d_in[1];
    const float* gamma = (const float*)d_in[2];
    const float* beta  = (const float*)d_in[3];
    float* out = (float*)d_out;

    cudaFuncSetAttribute(gram_k, cudaFuncAttributeMaxDynamicSharedMemorySize,
                         GS_TOTAL);

    zero_stats_k<<<1, 64>>>();
    xx_k<<<(BB * NP) / 256, 256>>>(x);
    ac_k<<<dim3(NP / 128, BB), 256>>>(x, W);
    gram_k<<<dim3(NPAIRS, BB), 256, GS_TOTAL>>>(x);
    select2_k<<<(BB * NP) / 8, 256>>>();
    maxmin_k<<<(BB * NP) / 4, 256>>>();
    finalize_k<<<1, 64>>>(gamma, beta);
    out_k<<<dim3(NP / 64, BB), 256>>>(out);
}

// round 9
// speedup vs baseline: 2.9176x; 1.1548x over previous
#include <cuda_runtime.h>

typedef unsigned long long ull;
typedef unsigned int uint;

#define BB   8
#define NP   4096
#define CI   64
#define CO   64
#define KK   20
#define NTILE 32
#define NPAIRS (NTILE * (NTILE + 1) / 2)   // 528
#define TSTRIDE 132                         // transposed-tile stride (16B-aligned rows)

// ---------------- scratch (static device globals; no runtime allocation) ----
static __device__ float g_dist[(size_t)BB * NP * NP];   // 512 MB score rows
static __device__ float g_tmax[(size_t)BB * NP * NTILE];// per-(row, m-tile) max
static __device__ float g_xx[BB * NP];                  // squared norms
static __device__ int   g_idx[BB * NP * KK];            // knn indices
static __device__ float g_a [BB * NP * CO];             // (W1-W2) @ x_n
static __device__ float g_cc[BB * NP * CO];             // W2 @ x_m
static __device__ float g_hmax[(size_t)BB * NP * CO];
static __device__ float g_hmin[(size_t)BB * NP * CO];
static __device__ float g_sum[CO];
static __device__ float g_sumsq[CO];
static __device__ float g_scale[CO];
static __device__ float g_bias[CO];

// ---------------- helpers ---------------------------------------------------
__device__ __forceinline__ ull ffma2(ull a, ull b, ull c) {
    ull d;
    asm("fma.rn.f32x2 %0, %1, %2, %3;" : "=l"(d) : "l"(a), "l"(b), "l"(c));
    return d;
}
__device__ __forceinline__ ull dup2(float f) {
    unsigned u = __float_as_uint(f);
    return (ull)u | ((ull)u << 32);
}
__device__ __forceinline__ void cp16(uint s, const void* g) {
    asm volatile("cp.async.cg.shared.global [%0], [%1], 16;" :: "r"(s), "l"(g));
}
__device__ __forceinline__ void cp_commit() {
    asm volatile("cp.async.commit_group;");
}
__device__ __forceinline__ void cp_wait0() {
    asm volatile("cp.async.wait_group 0;" ::: "memory");
}

// ---------------- 0: zero channel stats -------------------------------------
__global__ void zero_stats_k() {
    int t = threadIdx.x;
    if (t < CO) { g_sum[t] = 0.f; g_sumsq[t] = 0.f; }
}

// ---------------- 1: squared norms ------------------------------------------
__global__ void xx_k(const float* __restrict__ x) {
    int g = blockIdx.x * blockDim.x + threadIdx.x;     // 0..BB*NP-1
    int b = g >> 12;
    int n = g & (NP - 1);
    const float* xb = x + (size_t)b * CI * NP + n;
    float s = 0.f;
    #pragma unroll
    for (int c = 0; c < CI; ++c) { float v = xb[c * NP]; s = fmaf(v, v, s); }
    g_xx[g] = s;
}

// ---------------- 2: a = (W1-W2)@x_n,  c = W2@x_n ---------------------------
__global__ __launch_bounds__(256) void ac_k(const float* __restrict__ x,
                                            const float* __restrict__ W) {
    __shared__ float sWd[CI * CO];   // [c][o]
    __shared__ float sW2[CI * CO];   // [c][o]
    int tid = threadIdx.x;
    for (int i = tid; i < CI * CO; i += 256) {
        int o = i >> 6, c = i & 63;
        float w1 = W[o * 128 + c];
        float w2 = W[o * 128 + 64 + c];
        sWd[c * CO + o] = w1 - w2;
        sW2[c * CO + o] = w2;
    }
    __syncthreads();
    int b  = blockIdx.y;
    int n  = blockIdx.x * 128 + (tid & 127);
    int o0 = (tid >> 7) * 32;
    float aa[32], cc[32];
    #pragma unroll
    for (int j = 0; j < 32; ++j) { aa[j] = 0.f; cc[j] = 0.f; }
    const float* xb = x + (size_t)b * CI * NP + n;
    for (int c = 0; c < CI; ++c) {
        float xv = xb[c * NP];
        const float4* wd4 = (const float4*)(sWd + c * CO + o0);
        const float4* w24 = (const float4*)(sW2 + c * CO + o0);
        #pragma unroll
        for (int j4 = 0; j4 < 8; ++j4) {
            float4 wd = wd4[j4], w2 = w24[j4];
            aa[j4*4+0] = fmaf(xv, wd.x, aa[j4*4+0]);
            aa[j4*4+1] = fmaf(xv, wd.y, aa[j4*4+1]);
            aa[j4*4+2] = fmaf(xv, wd.z, aa[j4*4+2]);
            aa[j4*4+3] = fmaf(xv, wd.w, aa[j4*4+3]);
            cc[j4*4+0] = fmaf(xv, w2.x, cc[j4*4+0]);
            cc[j4*4+1] = fmaf(xv, w2.y, cc[j4*4+1]);
            cc[j4*4+2] = fmaf(xv, w2.z, cc[j4*4+2]);
            cc[j4*4+3] = fmaf(xv, w2.w, cc[j4*4+3]);
        }
    }
    size_t base = ((size_t)b * NP + n) * CO + o0;
    #pragma unroll
    for (int j = 0; j < 32; ++j) { g_a[base + j] = aa[j]; g_cc[base + j] = cc[j]; }
}

// ---------------- 3: Gram (triangular tile pairs) + per-(row,tile) max ------
#define GS_TOTAL (128 * TSTRIDE * 4)    // 67,584 B (>= sQ 32KB + sP 32KB)

__global__ __launch_bounds__(256, 2) void gram_k(const float* __restrict__ x) {
    extern __shared__ char smraw[];
    float* sQ = (float*)smraw;              // [c][128] rows-tile (ti)
    float* sP = sQ + 64 * 128;              // [c][128] cols-tile (tj)
    const int tid = threadIdx.x;
    const int b   = blockIdx.y;
    // decode pair index -> (ti, tj), ti <= tj, p = tj*(tj+1)/2 + ti
    int p  = blockIdx.x;
    int tj = (int)((sqrtf(8.f * p + 1.f) - 1.f) * 0.5f);
    while ((tj + 1) * (tj + 2) / 2 <= p) ++tj;
    while (tj * (tj + 1) / 2 > p) --tj;
    int ti = p - tj * (tj + 1) / 2;
    const int n0 = ti << 7;
    const int m0 = tj << 7;
    const float* xb = x + (size_t)b * CI * NP;

    {
        uint sq = (uint)__cvta_generic_to_shared(sQ);
        uint sp = (uint)__cvta_generic_to_shared(sP);
        #pragma unroll
        for (int k = 0; k < 8; ++k) {
            int i = k * 256 + tid;           // 0..2047
            int c = i >> 5, j = (i & 31) << 2;
            uint off = (uint)(c * 128 + j) * 4;
            cp16(sq + off, xb + (size_t)c * NP + n0 + j);
            cp16(sp + off, xb + (size_t)c * NP + m0 + j);
        }
        cp_commit();
    }

    const int tx = tid & 15;      // m-pair: pr = tx + 16*g  ->  m = 2pr, 2pr+1
    const int ty = tid >> 4;      // n: row = ty*8 + i
    const float* xxg = g_xx + b * NP;

    ull acc[8][4];
    #pragma unroll
    for (int i = 0; i < 8; ++i)
        #pragma unroll
        for (int g = 0; g < 4; ++g) acc[i][g] = 0ull;

    cp_wait0();
    __syncthreads();

    #pragma unroll 4
    for (int c = 0; c < CI; ++c) {
        const float* qp = sQ + c * 128 + ty * 8;
        float4 qa = *(const float4*)qp;          // LDS.128 (broadcast per ty)
        float4 qb = *(const float4*)(qp + 4);
        ull q[8];
        q[0] = dup2(qa.x); q[1] = dup2(qa.y); q[2] = dup2(qa.z); q[3] = dup2(qa.w);
        q[4] = dup2(qb.x); q[5] = dup2(qb.y); q[6] = dup2(qb.z); q[7] = dup2(qb.w);
        ull pp[4];
        const ull* pr = (const ull*)(sP + c * 128);
        #pragma unroll
        for (int g = 0; g < 4; ++g) pp[g] = pr[tx + (g << 4)];
        #pragma unroll
        for (int i = 0; i < 8; ++i)
            #pragma unroll
            for (int g = 0; g < 4; ++g) acc[i][g] = ffma2(q[i], pp[g], acc[i][g]);
    }

    // ---- direct orientation: rows n0-strip, cols m0-strip ----
    size_t rb = (size_t)b * NP + n0 + ty * 8;
    float2 wng[4];
    #pragma unroll
    for (int g = 0; g < 4; ++g) {
        float2 w = *(const float2*)(xxg + m0 + ((tx + (g << 4)) << 1));
        wng[g].x = -0.5f * w.x; wng[g].y = -0.5f * w.y;
    }
    #pragma unroll
    for (int i = 0; i < 8; ++i) {
        float rmax = __int_as_float(0xff800000);
        #pragma unroll
        for (int g = 0; g < 4; ++g) {
            int mp = tx + (g << 4);
            float2 v;
            v.x = __uint_as_float((unsigned)(acc[i][g]))       + wng[g].x;
            v.y = __uint_as_float((unsigned)(acc[i][g] >> 32)) + wng[g].y;
            *(float2*)(g_dist + (rb + i) * NP + m0 + (mp << 1)) = v;
            rmax = fmaxf(rmax, fmaxf(v.x, v.y));
        }
        #pragma unroll
        for (int off = 8; off; off >>= 1)
            rmax = fmaxf(rmax, __shfl_xor_sync(0xffffffffu, rmax, off));
        if (tx == 0) g_tmax[(rb + i) * NTILE + tj] = rmax;
    }

    // ---- transposed orientation (off-diagonal pairs only) ----
    if (ti != tj) {
        __syncthreads();                       // operand smem now reusable
        float* sT = sQ;                        // [m][n] tile, stride TSTRIDE
        #pragma unroll
        for (int i = 0; i < 8; ++i) {
            int nloc = ty * 8 + i;
            #pragma unroll
            for (int g = 0; g < 4; ++g) {
                int mloc = (tx + (g << 4)) << 1;
                sT[mloc * TSTRIDE + nloc]       = __uint_as_float((unsigned)(acc[i][g]));
                sT[(mloc + 1) * TSTRIDE + nloc] = __uint_as_float((unsigned)(acc[i][g] >> 32));
            }
        }
        __syncthreads();
        int r = tid >> 1, h = tid & 1;         // row m-local, interleaved half
        const float* rowT = sT + r * TSTRIDE;
        float rmax = __int_as_float(0xff800000);
        size_t gb = ((size_t)b * NP + m0 + r) * NP + n0;
        #pragma unroll
        for (int k = 0; k < 16; ++k) {
            int col = (k << 3) + (h << 2);
            float4 v = *(const float4*)(rowT + col);
            float4 xv = *(const float4*)(xxg + n0 + col);
            v.x = fmaf(-0.5f, xv.x, v.x);
            v.y = fmaf(-0.5f, xv.y, v.y);
            v.z = fmaf(-0.5f, xv.z, v.z);
            v.w = fmaf(-0.5f, xv.w, v.w);
            *(float4*)(g_dist + gb + col) = v;
            rmax = fmaxf(rmax, fmaxf(fmaxf(v.x, v.y), fmaxf(v.z, v.w)));
        }
        rmax = fmaxf(rmax, __shfl_xor_sync(0xffffffffu, rmax, 1));
        if (h == 0) g_tmax[((size_t)b * NP + m0 + r) * NTILE + ti] = rmax;
    }
}

// ---------------- 4: pruned top-20 select (threshold-seeded) -----------------
__global__ __launch_bounds__(256) void select2_k() {
    const int row  = (blockIdx.x * 256 + threadIdx.x) >> 5;
    const int lane = threadIdx.x & 31;
    const float NEG = __int_as_float(0xff800000);
    const unsigned FULL = 0xffffffffu;

    float tmv = g_tmax[(size_t)row * NTILE + lane]; // one tile-max per lane

    // thr0 = 20th largest tile-max: a valid lower bound on the 20th-largest
    // score (the 20 largest tile-maxima are attained by 20 distinct elements).
    float thr0;
    {
        float s = tmv;
        #pragma unroll
        for (int k = 2; k <= 32; k <<= 1)
            #pragma unroll
            for (int j = k >> 1; j; j >>= 1) {
                float t = __shfl_xor_sync(FULL, s, j);
                bool asc   = ((lane & k) == 0);
                bool lower = ((lane & j) == 0);
                float mn = fminf(s, t), mx = fmaxf(s, t);
                s = (asc == lower) ? mn : mx;      // ascending by lane
            }
        thr0 = __shfl_sync(FULL, s, 12);           // lane 31-19
    }

    float lv = NEG; int li = 0;                     // distributed sorted list
    float thr = NEG;                                // = lv[19]
    const float* base = g_dist + (size_t)row * NP;

    for (int it = 0; it < NTILE; ++it) {
        float bv = tmv; int bt = lane;
        #pragma unroll
        for (int off = 16; off; off >>= 1) {
            float ov = __shfl_xor_sync(FULL, bv, off);
            int   ot = __shfl_xor_sync(FULL, bt, off);
            if (ov > bv || (ov == bv && ot < bt)) { bv = ov; bt = ot; }
        }
        if (bv < thr0 || bv <= thr) break;
        if (lane == bt) tmv = NEG;

        float4 v4 = *(const float4*)(base + (bt << 7) + (lane << 2));
        int ib = (bt << 7) + (lane << 2);
        #pragma unroll
        for (int e = 0; e < 4; ++e) {
            float v = (e == 0) ? v4.x : (e == 1) ? v4.y : (e == 2) ? v4.z : v4.w;
            bool pend = (v >= thr0) && (v > thr);
            while (true) {
                unsigned ball = __ballot_sync(FULL, pend);
                if (!ball) break;
                int   src = __ffs(ball) - 1;
                float cv  = __shfl_sync(FULL, v, src);
                int   ci  = __shfl_sync(FULL, ib + e, src);
                unsigned gb = __ballot_sync(FULL, lane < KK && lv >= cv);
                int pos = __popc(gb);
                float sv = __shfl_up_sync(FULL, lv, 1);
                int   si = __shfl_up_sync(FULL, li, 1);
                if (lane > pos)       { lv = sv; li = si; }
                else if (lane == pos) { lv = cv; li = ci; }
                thr = __shfl_sync(FULL, lv, KK - 1);
                if (lane == src) pend = false;
                pend = pend && (v > thr);
            }
        }
    }
    if (lane < KK) g_idx[(size_t)row * KK + lane] = li;
}

// ---------------- 5: per-(b,n,o) max/min over k + channel stats -------------
__global__ __launch_bounds__(256) void maxmin_k() {
    __shared__ float sSum[CO], sSq[CO];
    int tid = threadIdx.x;
    if (tid < CO) { sSum[tid] = 0.f; sSq[tid] = 0.f; }
    __syncthreads();
    int o = tid & 63;
    int r = blockIdx.x * 4 + (tid >> 6);       // row = b*NP+n
    int b = r >> 12;
    float av = g_a[(size_t)r * CO + o];
    const int* ip = g_idx + (size_t)r * KK;
    const float PINF = __int_as_float(0x7f800000);
    float mx = -PINF, mn = PINF, s = 0.f, s2 = 0.f;
    #pragma unroll
    for (int k = 0; k < KK; ++k) {
        int j = ip[k];
        float e = av + g_cc[((size_t)(b << 12) + j) * CO + o];
        mx = fmaxf(mx, e); mn = fminf(mn, e);
        s += e; s2 = fmaf(e, e, s2);
    }
    g_hmax[(size_t)r * CO + o] = mx;
    g_hmin[(size_t)r * CO + o] = mn;
    atomicAdd(&sSum[o], s);
    atomicAdd(&sSq[o], s2);
    __syncthreads();
    if (tid < CO) {
        atomicAdd(&g_sum[tid], sSum[tid]);
        atomicAdd(&g_sumsq[tid], sSq[tid]);
    }
}

// ---------------- 6: finalize batchnorm affine ------------------------------
__global__ void finalize_k(const float* __restrict__ gamma,
                           const float* __restrict__ beta) {
    int o = threadIdx.x;
    const float cnt = (float)BB * NP * KK;
    float mean = g_sum[o] / cnt;
    float var  = g_sumsq[o] / cnt - mean * mean;
    float sc   = gamma[o] * rsqrtf(var + 1e-5f);
    g_scale[o] = sc;
    g_bias[o]  = fmaf(-mean, sc, beta[o]);
}

// ---------------- 7: output (affine + leaky + transpose to (B,CO,N)) --------
__global__ __launch_bounds__(256) void out_k(float* __restrict__ out) {
    __shared__ float sm[64][65];
    int tid = threadIdx.x;
    int b = blockIdx.y, n0 = blockIdx.x * 64;
    #pragma unroll
    for (int it = 0; it < 16; ++it) {
        int i = it * 4 + (tid >> 6), o = tid & 63;
        float sc = g_scale[o];
        size_t idx = ((size_t)b * NP + n0 + i) * CO + o;
        float h = (sc >= 0.f) ? g_hmax[idx] : g_hmin[idx];
        float v = fmaf(sc, h, g_bias[o]);
        sm[i][o] = (v >= 0.f) ? v : 0.2f * v;
    }
    __syncthreads();
    #pragma unroll
    for (int it = 0; it < 16; ++it) {
        int o = it * 4 + (tid >> 6), n = tid & 63;
        out[((size_t)b * CO + o) * NP + n0 + n] = sm[n][o];
    }
}

// ---------------- launch -----------------------------------------------------
extern "C" void kernel_launch(void* const* d_in, const int* in_sizes, int n_in,
                              void* d_out, int out_size) {
    const float* x     = (const float*)d_in[0];
    const float* W     = (const float*)d_in[1];
    const float* gamma = (const float*)d_in[2];
    const float* beta  = (const float*)d_in[3];
    float* out = (float*)d_out;

    cudaFuncSetAttribute(gram_k, cudaFuncAttributeMaxDynamicSharedMemorySize,
                         GS_TOTAL);

    zero_stats_k<<<1, 64>>>();
    xx_k<<<(BB * NP) / 256, 256>>>(x);
    ac_k<<<dim3(NP / 128, BB), 256>>>(x, W);
    gram_k<<<dim3(NPAIRS, BB), 256, GS_TOTAL>>>(x);
    select2_k<<<(BB * NP) / 8, 256>>>();
    maxmin_k<<<(BB * NP) / 4, 256>>>();
    finalize_k<<<1, 64>>>(gamma, beta);
    out_k<<<dim3(NP / 64, BB), 256>>>(out);
}